// round 2
// baseline (speedup 1.0000x reference)
#include <cuda_runtime.h>
#include <cstdint>

#define NROWS 65536
#define DDIM  512
#define EDIM  256
#define TDIM  128
#define KDIM  896   // D + E + T
#define NPROTO 5

// Scratch for GEMM output (128 MB). __device__ global per harness rules.
__device__ float g_y[(size_t)NROWS * DDIM];

// ---------------------------------------------------------------------------
// GEMM: g_y[N, 512] = concat(raw, edge, time)[N, 896] @ Wq^T   (TF32 MMA)
// ---------------------------------------------------------------------------
constexpr int BM = 128, BN = 128, BK = 32;
constexpr int LDSW  = BK + 4;             // 36-float row stride (conflict-free frags)
constexpr int STAGE = (BM + BN) * LDSW;   // floats per pipeline stage
constexpr int SMEM_BYTES = 2 * STAGE * 4; // 73728 B (double buffered)

__device__ __forceinline__ void cp16(uint32_t saddr, const void* gaddr) {
    asm volatile("cp.async.cg.shared.global [%0], [%1], 16;\n" :: "r"(saddr), "l"(gaddr));
}

__global__ void __launch_bounds__(256, 2)
gemm_kernel(const float* __restrict__ raw, const float* __restrict__ edge,
            const float* __restrict__ te,  const float* __restrict__ Wq) {
    extern __shared__ float sm[];
    const int tid  = threadIdx.x;
    const int m0   = blockIdx.y * BM;
    const int n0   = blockIdx.x * BN;
    const int warp = tid >> 5, lane = tid & 31;
    const int wm   = warp & 3, wn = warp >> 2;   // 4 warps along M, 2 along N
    const int g    = lane >> 2, t = lane & 3;

    float acc[2][8][4];
    #pragma unroll
    for (int mi = 0; mi < 2; mi++)
        #pragma unroll
        for (int ni = 0; ni < 8; ni++)
            #pragma unroll
            for (int j = 0; j < 4; j++) acc[mi][ni][j] = 0.f;

    auto issue = [&](int kt) {
        float* As = sm + (kt & 1) * STAGE;
        float* Bs = As + BM * LDSW;
        const float* aBase; int stride, col0;
        if (kt < 16)      { aBase = raw;  stride = DDIM; col0 = kt * 32; }
        else if (kt < 24) { aBase = edge; stride = EDIM; col0 = (kt - 16) * 32; }
        else              { aBase = te;   stride = TDIM; col0 = (kt - 24) * 32; }
        #pragma unroll
        for (int i = 0; i < 4; i++) {
            int idx = tid + i * 256;
            int r = idx >> 3, c = (idx & 7) * 4;
            cp16((uint32_t)__cvta_generic_to_shared(As + r * LDSW + c),
                 aBase + (size_t)(m0 + r) * stride + col0 + c);
            cp16((uint32_t)__cvta_generic_to_shared(Bs + r * LDSW + c),
                 Wq + (size_t)(n0 + r) * KDIM + kt * 32 + c);
        }
        asm volatile("cp.async.commit_group;\n");
    };

    issue(0);
    for (int kt = 0; kt < 28; kt++) {
        if (kt < 27) {
            issue(kt + 1);
            asm volatile("cp.async.wait_group 1;\n");
        } else {
            asm volatile("cp.async.wait_group 0;\n");
        }
        __syncthreads();

        const float* As = sm + (kt & 1) * STAGE;
        const float* Bs = As + BM * LDSW;
        #pragma unroll
        for (int ks = 0; ks < 4; ks++) {
            const int kk = ks * 8;
            uint32_t a[2][4], b[8][2];
            #pragma unroll
            for (int mi = 0; mi < 2; mi++) {
                const float* ap = As + (wm * 32 + mi * 16 + g) * LDSW + kk + t;
                a[mi][0] = __float_as_uint(ap[0]);
                a[mi][1] = __float_as_uint(ap[8 * LDSW]);
                a[mi][2] = __float_as_uint(ap[4]);
                a[mi][3] = __float_as_uint(ap[8 * LDSW + 4]);
            }
            #pragma unroll
            for (int ni = 0; ni < 8; ni++) {
                const float* bp = Bs + (wn * 64 + ni * 8 + g) * LDSW + kk + t;
                b[ni][0] = __float_as_uint(bp[0]);
                b[ni][1] = __float_as_uint(bp[4]);
            }
            #pragma unroll
            for (int mi = 0; mi < 2; mi++)
                #pragma unroll
                for (int ni = 0; ni < 8; ni++) {
                    float* c = acc[mi][ni];
                    asm volatile(
                        "mma.sync.aligned.m16n8k8.row.col.f32.tf32.tf32.f32 "
                        "{%0,%1,%2,%3}, {%4,%5,%6,%7}, {%8,%9}, {%0,%1,%2,%3};\n"
                        : "+f"(c[0]), "+f"(c[1]), "+f"(c[2]), "+f"(c[3])
                        : "r"(a[mi][0]), "r"(a[mi][1]), "r"(a[mi][2]), "r"(a[mi][3]),
                          "r"(b[ni][0]), "r"(b[ni][1]));
                }
        }
        __syncthreads();
    }

    // Writeback (c0,c1 adjacent columns -> float2)
    #pragma unroll
    for (int mi = 0; mi < 2; mi++) {
        int r0 = m0 + wm * 32 + mi * 16 + g;
        #pragma unroll
        for (int ni = 0; ni < 8; ni++) {
            int c = n0 + wn * 64 + ni * 8 + t * 2;
            *reinterpret_cast<float2*>(g_y + (size_t)r0 * DDIM + c) =
                make_float2(acc[mi][ni][0], acc[mi][ni][1]);
            *reinterpret_cast<float2*>(g_y + (size_t)(r0 + 8) * DDIM + c) =
                make_float2(acc[mi][ni][2], acc[mi][ni][3]);
        }
    }
}

// ---------------------------------------------------------------------------
// Fused epilogue: one block (512 threads) per row.
// LN -> tanh -> cosine sim vs 5 prototypes -> softmax -> cand -> gate -> LN
// ---------------------------------------------------------------------------
template <int NV>
__device__ __forceinline__ void blk_reduce(float* v, float* red, int tid) {
    const int lane = tid & 31, wid = tid >> 5;
    #pragma unroll
    for (int j = 0; j < NV; j++) {
        float x = v[j];
        #pragma unroll
        for (int o = 16; o > 0; o >>= 1) x += __shfl_xor_sync(0xffffffffu, x, o);
        if (lane == 0) red[wid * NV + j] = x;
    }
    __syncthreads();
    if (tid < NV) {
        float s = 0.f;
        #pragma unroll
        for (int w = 0; w < 16; w++) s += red[w * NV + tid];
        red[tid] = s;  // red[tid] only read (w=0) and written by thread tid
    }
    __syncthreads();
    #pragma unroll
    for (int j = 0; j < NV; j++) v[j] = red[j];
    __syncthreads();
}

__device__ __forceinline__ float clampf(float x, float a) { return fminf(fmaxf(x, -a), a); }

__global__ void __launch_bounds__(512)
epilogue_kernel(const float* __restrict__ raw, const float* __restrict__ te,
                const float* __restrict__ protos, const float* __restrict__ bq,
                const float* __restrict__ Wg, const float* __restrict__ bg,
                const float* __restrict__ gam, const float* __restrict__ bet,
                const float* __restrict__ temperature, float* __restrict__ out) {
    __shared__ float red[16 * 11];
    const int row = blockIdx.x;
    const int d = threadIdx.x;
    const size_t base = (size_t)row * DDIM;

    float s[11];

    // LN1 over GEMM result (+bq), then tanh -> query
    float yv = g_y[base + d] + bq[d];
    s[0] = yv; s[1] = yv * yv;
    blk_reduce<2>(s, red, d);
    float mean = s[0] * (1.f / DDIM);
    float var  = s[1] * (1.f / DDIM) - mean * mean;
    float q  = tanhf((yv - mean) * rsqrtf(var + 1e-6f) * gam[d] + bet[d]);
    float qs = clampf(q, 20.f);

    // Fused reduction: |q|^2, |p_k|^2 (k=0..4), q.p_k (k=0..4)
    float p[NPROTO];
    s[0] = qs * qs;
    #pragma unroll
    for (int k = 0; k < NPROTO; k++) {
        p[k] = protos[(size_t)row * (NPROTO * DDIM) + k * DDIM + d];
        float ps = clampf(p[k], 20.f);
        s[1 + k] = ps * ps;
        s[6 + k] = qs * ps;
    }
    blk_reduce<11>(s, red, d);

    // cosine sims -> softmax over K=5 (computed redundantly per thread)
    float qn  = fmaxf(sqrtf(s[0]), 1e-6f);
    float tmp = fminf(fmaxf(temperature[0], 0.5f), 5.f) + 1e-4f;
    float sim[NPROTO], mx = -1e30f;
    #pragma unroll
    for (int k = 0; k < NPROTO; k++) {
        float pn = fmaxf(sqrtf(s[1 + k]), 1e-6f);
        float sv = clampf(s[6 + k] / (qn * pn), 15.f) / tmp;
        sim[k] = sv; mx = fmaxf(mx, sv);
    }
    float den = 0.f;
    #pragma unroll
    for (int k = 0; k < NPROTO; k++) { sim[k] = expf(sim[k] - mx); den += sim[k]; }
    float inv = 1.f / den;
    float cand = 0.f;
    #pragma unroll
    for (int k = 0; k < NPROTO; k++) cand += sim[k] * inv * p[k];
    cand = clampf(cand, 5.f);

    // Gate: Wg . clip([raw, cand, time_raw], +-30) + bg
    float rawv = clampf(raw[base + d], 50.f);
    float gsum = Wg[d] * clampf(rawv, 30.f) + Wg[DDIM + d] * cand;  // |cand|<=5
    if (d < TDIM) {
        float tv = te[(size_t)row * TDIM + d];   // un-sanitized time, then clip 30
        gsum += Wg[2 * DDIM + d] * clampf(tv, 30.f);
    }
    s[0] = gsum;
    blk_reduce<1>(s, red, d);
    float logit = clampf(s[0] + bg[0], 10.f);
    float gg = 1.f / (1.f + expf(-logit));

    // Blend + final LN + clip
    float gated = (1.f - gg) * rawv + gg * cand;
    float upd   = 0.8f * rawv + 0.2f * gated;
    s[0] = upd; s[1] = upd * upd;
    blk_reduce<2>(s, red, d);
    mean = s[0] * (1.f / DDIM);
    var  = s[1] * (1.f / DDIM) - mean * mean;
    float o = (upd - mean) * rsqrtf(var + 1e-6f) * gam[d] + bet[d];
    out[base + d] = clampf(o, 10.f);
}

// ---------------------------------------------------------------------------
extern "C" void kernel_launch(void* const* d_in, const int* in_sizes, int n_in,
                              void* d_out, int out_size) {
    (void)in_sizes; (void)n_in; (void)out_size;
    const float* raw  = (const float*)d_in[0];
    // d_in[1] = node_features: unused by the reference computation
    const float* edge = (const float*)d_in[2];
    const float* te   = (const float*)d_in[3];
    const float* prot = (const float*)d_in[4];
    const float* Wq   = (const float*)d_in[5];
    const float* bq   = (const float*)d_in[6];
    const float* Wg   = (const float*)d_in[7];
    const float* bg   = (const float*)d_in[8];
    const float* gam  = (const float*)d_in[9];
    const float* bet  = (const float*)d_in[10];
    const float* temp = (const float*)d_in[11];
    float* out = (float*)d_out;

    cudaFuncSetAttribute(gemm_kernel, cudaFuncAttributeMaxDynamicSharedMemorySize, SMEM_BYTES);
    gemm_kernel<<<dim3(4, 512), 256, SMEM_BYTES>>>(raw, edge, te, Wq);
    epilogue_kernel<<<NROWS, 512>>>(raw, te, prot, bq, Wg, bg, gam, bet, temp, out);
}

// round 6
// speedup vs baseline: 2.3009x; 2.3009x over previous
#include <cuda_runtime.h>
#include <cstdint>

#define NROWS 65536
#define DDIM  512
#define EDIM  256
#define TDIM  128
#define KDIM  896   // D + E + T
#define NPROTO 5

// Scratch for GEMM output (128 MB). __device__ global per harness rules.
__device__ float g_y[(size_t)NROWS * DDIM];

// ---------------------------------------------------------------------------
// GEMM: g_y[N, 512] = concat(raw, edge, time)[N, 896] @ Wq^T   (TF32 MMA)
// ---------------------------------------------------------------------------
constexpr int BM = 128, BN = 128, BK = 32;
constexpr int LDSW  = BK + 4;             // 36-float row stride (conflict-free frags)
constexpr int STAGE = (BM + BN) * LDSW;   // floats per pipeline stage
constexpr int SMEM_BYTES = 2 * STAGE * 4; // 73728 B (double buffered)

__device__ __forceinline__ void cp16(uint32_t saddr, const void* gaddr) {
    asm volatile("cp.async.cg.shared.global [%0], [%1], 16;\n" :: "r"(saddr), "l"(gaddr));
}

__global__ void __launch_bounds__(256, 2)
gemm_kernel(const float* __restrict__ raw, const float* __restrict__ edge,
            const float* __restrict__ te,  const float* __restrict__ Wq) {
    extern __shared__ float sm[];
    const int tid  = threadIdx.x;
    const int m0   = blockIdx.y * BM;
    const int n0   = blockIdx.x * BN;
    const int warp = tid >> 5, lane = tid & 31;
    const int wm   = warp & 3, wn = warp >> 2;   // 4 warps along M, 2 along N
    const int g    = lane >> 2, t = lane & 3;

    float acc[2][8][4];
    #pragma unroll
    for (int mi = 0; mi < 2; mi++)
        #pragma unroll
        for (int ni = 0; ni < 8; ni++)
            #pragma unroll
            for (int j = 0; j < 4; j++) acc[mi][ni][j] = 0.f;

    auto issue = [&](int kt) {
        float* As = sm + (kt & 1) * STAGE;
        float* Bs = As + BM * LDSW;
        const float* aBase; int stride, col0;
        if (kt < 16)      { aBase = raw;  stride = DDIM; col0 = kt * 32; }
        else if (kt < 24) { aBase = edge; stride = EDIM; col0 = (kt - 16) * 32; }
        else              { aBase = te;   stride = TDIM; col0 = (kt - 24) * 32; }
        #pragma unroll
        for (int i = 0; i < 4; i++) {
            int idx = tid + i * 256;
            int r = idx >> 3, c = (idx & 7) * 4;
            cp16((uint32_t)__cvta_generic_to_shared(As + r * LDSW + c),
                 aBase + (size_t)(m0 + r) * stride + col0 + c);
            cp16((uint32_t)__cvta_generic_to_shared(Bs + r * LDSW + c),
                 Wq + (size_t)(n0 + r) * KDIM + kt * 32 + c);
        }
        asm volatile("cp.async.commit_group;\n");
    };

    issue(0);
    for (int kt = 0; kt < 28; kt++) {
        if (kt < 27) {
            issue(kt + 1);
            asm volatile("cp.async.wait_group 1;\n");
        } else {
            asm volatile("cp.async.wait_group 0;\n");
        }
        __syncthreads();

        const float* As = sm + (kt & 1) * STAGE;
        const float* Bs = As + BM * LDSW;
        #pragma unroll
        for (int ks = 0; ks < 4; ks++) {
            const int kk = ks * 8;
            uint32_t a[2][4], b[8][2];
            #pragma unroll
            for (int mi = 0; mi < 2; mi++) {
                const float* ap = As + (wm * 32 + mi * 16 + g) * LDSW + kk + t;
                a[mi][0] = __float_as_uint(ap[0]);
                a[mi][1] = __float_as_uint(ap[8 * LDSW]);
                a[mi][2] = __float_as_uint(ap[4]);
                a[mi][3] = __float_as_uint(ap[8 * LDSW + 4]);
            }
            #pragma unroll
            for (int ni = 0; ni < 8; ni++) {
                const float* bp = Bs + (wn * 64 + ni * 8 + g) * LDSW + kk + t;
                b[ni][0] = __float_as_uint(bp[0]);
                b[ni][1] = __float_as_uint(bp[4]);
            }
            #pragma unroll
            for (int mi = 0; mi < 2; mi++)
                #pragma unroll
                for (int ni = 0; ni < 8; ni++) {
                    float* c = acc[mi][ni];
                    asm volatile(
                        "mma.sync.aligned.m16n8k8.row.col.f32.tf32.tf32.f32 "
                        "{%0,%1,%2,%3}, {%4,%5,%6,%7}, {%8,%9}, {%0,%1,%2,%3};\n"
                        : "+f"(c[0]), "+f"(c[1]), "+f"(c[2]), "+f"(c[3])
                        : "r"(a[mi][0]), "r"(a[mi][1]), "r"(a[mi][2]), "r"(a[mi][3]),
                          "r"(b[ni][0]), "r"(b[ni][1]));
                }
        }
        __syncthreads();
    }

    // Writeback (c0,c1 adjacent columns -> float2)
    #pragma unroll
    for (int mi = 0; mi < 2; mi++) {
        int r0 = m0 + wm * 32 + mi * 16 + g;
        #pragma unroll
        for (int ni = 0; ni < 8; ni++) {
            int c = n0 + wn * 64 + ni * 8 + t * 2;
            *reinterpret_cast<float2*>(g_y + (size_t)r0 * DDIM + c) =
                make_float2(acc[mi][ni][0], acc[mi][ni][1]);
            *reinterpret_cast<float2*>(g_y + (size_t)(r0 + 8) * DDIM + c) =
                make_float2(acc[mi][ni][2], acc[mi][ni][3]);
        }
    }
}

// ---------------------------------------------------------------------------
// Fused epilogue v2: ONE WARP per row, zero __syncthreads.
// Each thread owns 16 columns (4 x float4, stride 128 floats).
// All reductions are shfl.bfly trees. Prototypes live in registers.
// ---------------------------------------------------------------------------
__device__ __forceinline__ float wredsum(float x) {
    #pragma unroll
    for (int o = 16; o > 0; o >>= 1) x += __shfl_xor_sync(0xffffffffu, x, o);
    return x;
}
__device__ __forceinline__ float clampf(float x, float a) { return fminf(fmaxf(x, -a), a); }
__device__ __forceinline__ float4 c4(float4 v, float a) {
    return make_float4(clampf(v.x,a), clampf(v.y,a), clampf(v.z,a), clampf(v.w,a));
}

constexpr int EPI_WARPS = 4;   // rows per block

__global__ void __launch_bounds__(EPI_WARPS * 32)
epilogue_kernel(const float* __restrict__ raw, const float* __restrict__ te,
                const float* __restrict__ protos, const float* __restrict__ bq,
                const float* __restrict__ Wg, const float* __restrict__ bg,
                const float* __restrict__ gam, const float* __restrict__ bet,
                const float* __restrict__ temperature, float* __restrict__ out) {
    const int lane = threadIdx.x & 31;
    const int row  = blockIdx.x * EPI_WARPS + (threadIdx.x >> 5);
    const size_t base4 = (size_t)row * (DDIM / 4);   // float4 units

    const float4* y4p = reinterpret_cast<const float4*>(g_y) + base4;
    const float4* r4p = reinterpret_cast<const float4*>(raw) + base4;
    const float4* p4p = reinterpret_cast<const float4*>(protos) + (size_t)row * (NPROTO * DDIM / 4);
    const float4* bq4 = reinterpret_cast<const float4*>(bq);
    const float4* g4  = reinterpret_cast<const float4*>(gam);
    const float4* b4  = reinterpret_cast<const float4*>(bet);
    const float4* w4  = reinterpret_cast<const float4*>(Wg);

    // ---- LN1 input: y + bq ----
    float4 yv[4];
    float s0 = 0.f, s1 = 0.f;
    #pragma unroll
    for (int j = 0; j < 4; j++) {
        float4 v = y4p[lane + 32 * j];
        float4 b = bq4[lane + 32 * j];
        v.x += b.x; v.y += b.y; v.z += b.z; v.w += b.w;
        yv[j] = v;
        s0 += v.x + v.y + v.z + v.w;
        s1 += v.x*v.x + v.y*v.y + v.z*v.z + v.w*v.w;
    }
    s0 = wredsum(s0); s1 = wredsum(s1);
    float mean = s0 * (1.f / DDIM);
    float rstd = rsqrtf(s1 * (1.f / DDIM) - mean * mean + 1e-6f);

    // ---- q = tanh(LN(y)); |q|<=1 so the +-20 clip is a no-op ----
    float4 qv[4];
    float sqq = 0.f;
    #pragma unroll
    for (int j = 0; j < 4; j++) {
        float4 gm = g4[lane + 32 * j], bt = b4[lane + 32 * j];
        float4 q;
        q.x = tanhf((yv[j].x - mean) * rstd * gm.x + bt.x);
        q.y = tanhf((yv[j].y - mean) * rstd * gm.y + bt.y);
        q.z = tanhf((yv[j].z - mean) * rstd * gm.z + bt.z);
        q.w = tanhf((yv[j].w - mean) * rstd * gm.w + bt.w);
        qv[j] = q;
        sqq += q.x*q.x + q.y*q.y + q.z*q.z + q.w*q.w;
    }

    // ---- prototypes: |p_k|^2 and q.p_k, p kept in registers ----
    float4 pk[NPROTO][4];
    float spp[NPROTO], sqp[NPROTO];
    #pragma unroll
    for (int k = 0; k < NPROTO; k++) {
        float app = 0.f, aqp = 0.f;
        #pragma unroll
        for (int j = 0; j < 4; j++) {
            float4 v = p4p[k * (DDIM / 4) + lane + 32 * j];
            pk[k][j] = v;
            float4 c = c4(v, 20.f);
            app += c.x*c.x + c.y*c.y + c.z*c.z + c.w*c.w;
            aqp += qv[j].x*c.x + qv[j].y*c.y + qv[j].z*c.z + qv[j].w*c.w;
        }
        spp[k] = app; sqp[k] = aqp;
    }
    sqq = wredsum(sqq);
    #pragma unroll
    for (int k = 0; k < NPROTO; k++) { spp[k] = wredsum(spp[k]); sqp[k] = wredsum(sqp[k]); }

    // ---- cosine -> softmax (K=5, redundant per lane) ----
    float qn  = fmaxf(sqrtf(sqq), 1e-6f);
    float tmp = fminf(fmaxf(temperature[0], 0.5f), 5.f) + 1e-4f;
    float sim[NPROTO], mx = -1e30f;
    #pragma unroll
    for (int k = 0; k < NPROTO; k++) {
        float pn = fmaxf(sqrtf(spp[k]), 1e-6f);
        sim[k] = clampf(sqp[k] / (qn * pn), 15.f) / tmp;
        mx = fmaxf(mx, sim[k]);
    }
    float den = 0.f;
    #pragma unroll
    for (int k = 0; k < NPROTO; k++) { sim[k] = __expf(sim[k] - mx); den += sim[k]; }
    float inv = 1.f / den;
    #pragma unroll
    for (int k = 0; k < NPROTO; k++) sim[k] *= inv;

    // ---- cand + gate partial ----
    float4 cand[4], rw[4];
    float gs = 0.f;
    #pragma unroll
    for (int j = 0; j < 4; j++) {
        float4 c = make_float4(0.f, 0.f, 0.f, 0.f);
        #pragma unroll
        for (int k = 0; k < NPROTO; k++) {
            c.x += sim[k] * pk[k][j].x; c.y += sim[k] * pk[k][j].y;
            c.z += sim[k] * pk[k][j].z; c.w += sim[k] * pk[k][j].w;
        }
        c = c4(c, 5.f);
        cand[j] = c;
        float4 rv = c4(r4p[lane + 32 * j], 50.f);
        rw[j] = rv;
        float4 rc = c4(rv, 30.f);
        float4 wa = w4[lane + 32 * j];          // Wg[0:512]
        float4 wb = w4[128 + lane + 32 * j];    // Wg[512:1024]
        gs += wa.x*rc.x + wa.y*rc.y + wa.z*rc.z + wa.w*rc.w;
        gs += wb.x*c.x  + wb.y*c.y  + wb.z*c.z  + wb.w*c.w;
    }
    {   // time contribution: cols 0..127 live in j==0 slots
        float4 tv = c4(reinterpret_cast<const float4*>(te)[(size_t)row * (TDIM/4) + lane], 30.f);
        float4 wc = w4[256 + lane];             // Wg[1024:1152]
        gs += wc.x*tv.x + wc.y*tv.y + wc.z*tv.z + wc.w*tv.w;
    }
    gs = wredsum(gs);
    float logit = clampf(gs + bg[0], 10.f);
    float gg = 1.f / (1.f + __expf(-logit));

    // ---- blend + LN2 + clip ----
    float4 up[4];
    s0 = 0.f; s1 = 0.f;
    #pragma unroll
    for (int j = 0; j < 4; j++) {
        float4 u;
        u.x = 0.8f * rw[j].x + 0.2f * ((1.f - gg) * rw[j].x + gg * cand[j].x);
        u.y = 0.8f * rw[j].y + 0.2f * ((1.f - gg) * rw[j].y + gg * cand[j].y);
        u.z = 0.8f * rw[j].z + 0.2f * ((1.f - gg) * rw[j].z + gg * cand[j].z);
        u.w = 0.8f * rw[j].w + 0.2f * ((1.f - gg) * rw[j].w + gg * cand[j].w);
        up[j] = u;
        s0 += u.x + u.y + u.z + u.w;
        s1 += u.x*u.x + u.y*u.y + u.z*u.z + u.w*u.w;
    }
    s0 = wredsum(s0); s1 = wredsum(s1);
    mean = s0 * (1.f / DDIM);
    rstd = rsqrtf(s1 * (1.f / DDIM) - mean * mean + 1e-6f);
    float4* o4 = reinterpret_cast<float4*>(out) + base4;
    #pragma unroll
    for (int j = 0; j < 4; j++) {
        float4 gm = g4[lane + 32 * j], bt = b4[lane + 32 * j];
        float4 o;
        o.x = clampf((up[j].x - mean) * rstd * gm.x + bt.x, 10.f);
        o.y = clampf((up[j].y - mean) * rstd * gm.y + bt.y, 10.f);
        o.z = clampf((up[j].z - mean) * rstd * gm.z + bt.z, 10.f);
        o.w = clampf((up[j].w - mean) * rstd * gm.w + bt.w, 10.f);
        o4[lane + 32 * j] = o;
    }
}

// ---------------------------------------------------------------------------
extern "C" void kernel_launch(void* const* d_in, const int* in_sizes, int n_in,
                              void* d_out, int out_size) {
    (void)in_sizes; (void)n_in; (void)out_size;
    const float* raw  = (const float*)d_in[0];
    // d_in[1] = node_features: unused by the reference computation
    const float* edge = (const float*)d_in[2];
    const float* te   = (const float*)d_in[3];
    const float* prot = (const float*)d_in[4];
    const float* Wq   = (const float*)d_in[5];
    const float* bq   = (const float*)d_in[6];
    const float* Wg   = (const float*)d_in[7];
    const float* bg   = (const float*)d_in[8];
    const float* gam  = (const float*)d_in[9];
    const float* bet  = (const float*)d_in[10];
    const float* temp = (const float*)d_in[11];
    float* out = (float*)d_out;

    cudaFuncSetAttribute(gemm_kernel, cudaFuncAttributeMaxDynamicSharedMemorySize, SMEM_BYTES);
    gemm_kernel<<<dim3(4, 512), 256, SMEM_BYTES>>>(raw, edge, te, Wq);
    epilogue_kernel<<<NROWS / EPI_WARPS, EPI_WARPS * 32>>>(raw, te, prot, bq, Wg, bg, gam, bet, temp, out);
}